// round 5
// baseline (speedup 1.0000x reference)
#include <cuda_runtime.h>
#include <cuda_bf16.h>
#include <math.h>
#include <stdint.h>

// ---------------- Problem constants ----------------
#define BATCH 4
#define SEQ   2048
#define T_TOT (BATCH*SEQ)      // 8192
#define D_MODEL 768
#define L_LAYERS 4
#define N_STATE 16
#define K_CONV  4
#define I_INNER 1536           // 2*D_MODEL
#define DT_RANK 48
#define VOCAB 32000
#define EPS 1e-5f

// chunked scan config
#define CH_LEN 128
#define NCHUNK (SEQ / CH_LEN)   // 16

// ---------------- Scratch (static device globals; no allocs) ----------------
__device__ float g_h   [(size_t)T_TOT * D_MODEL];
__device__ float g_x   [(size_t)T_TOT * D_MODEL];
__device__ float g_proj[(size_t)T_TOT * 2 * I_INNER];
__device__ float g_ut  [(size_t)T_TOT * I_INNER];
__device__ float g_xdbl[(size_t)T_TOT * 80];
__device__ float g_dt  [(size_t)T_TOT * I_INNER];
__device__ float g_y   [(size_t)T_TOT * I_INNER];
__device__ float g_hn  [BATCH * D_MODEL];
// chunked-scan state: layout [b][c][i][n]
__device__ float g_pA  [(size_t)BATCH * NCHUNK * I_INNER * N_STATE];
__device__ float g_hf  [(size_t)BATCH * NCHUNK * I_INNER * N_STATE];
__device__ float g_hin [(size_t)BATCH * NCHUNK * I_INNER * N_STATE];

// ---------------- small helpers ----------------
__device__ __forceinline__ uint32_t smem_u32(const void* p) {
    uint32_t a;
    asm("{ .reg .u64 t; cvta.to.shared.u64 t, %1; cvt.u32.u64 %0, t; }"
        : "=r"(a) : "l"(p));
    return a;
}
__device__ __forceinline__ float tf32r(float x) {
    uint32_t r;
    asm("cvt.rna.tf32.f32 %0, %1;" : "=r"(r) : "f"(x));
    return __uint_as_float(r);
}
__device__ __forceinline__ void cp_async16(uint32_t dst, const void* src, int sz) {
    asm volatile("cp.async.cg.shared.global [%0], [%1], 16, %2;"
                 :: "r"(dst), "l"(src), "r"(sz) : "memory");
}
#define CP_COMMIT() asm volatile("cp.async.commit_group;" ::: "memory")
#define CP_WAIT2()  asm volatile("cp.async.wait_group 2;" ::: "memory")

__device__ __forceinline__ void mma_tf32(float* d, uint32_t a0, uint32_t a1,
                                         uint32_t a2, uint32_t a3,
                                         uint32_t b0, uint32_t b1) {
    asm volatile(
        "mma.sync.aligned.m16n8k8.row.col.f32.tf32.tf32.f32 "
        "{%0,%1,%2,%3}, {%4,%5,%6,%7}, {%8,%9}, {%0,%1,%2,%3};"
        : "+f"(d[0]), "+f"(d[1]), "+f"(d[2]), "+f"(d[3])
        : "r"(a0), "r"(a1), "r"(a2), "r"(a3), "r"(b0), "r"(b1));
}

__device__ __forceinline__ void ldsm_x4(uint32_t& r0, uint32_t& r1,
                                        uint32_t& r2, uint32_t& r3, uint32_t addr) {
    asm volatile("ldmatrix.sync.aligned.m8n8.x4.shared.b16 {%0,%1,%2,%3}, [%4];"
                 : "=r"(r0), "=r"(r1), "=r"(r2), "=r"(r3) : "r"(addr));
}

__device__ __forceinline__ float softplusf(float v) {
    return (v > 20.f) ? v : log1pf(__expf(v));
}

// ================= tensor-core tf32 GEMM (mma.sync m16n8k8 + ldmatrix) ======
// C[m,n] = sum_k A[m,k]*B[n,k].  A: 8192 x K rm, B: N x K rm.
// CTA tile 128x128, 8 warps (4m x 2n), warp tile 32x64, K chunks of 32,
// 3-stage cp.async pipeline, XOR-swizzled smem, ldmatrix fragment loads.
// EPI: 0 = store, 1 = C += acc, 2 = softplus(acc+bias), 3 = store tf32-rounded.
#define TG_SMEM (6 * 16384)

template<int EPI>
__global__ __launch_bounds__(256)
void tgemm(const float* __restrict__ A, int lda,
           const float* __restrict__ B, int ldb,
           float* __restrict__ C, int ldc,
           int N, int K, const float* __restrict__ bias) {
    extern __shared__ char smem[];
    const uint32_t sbA = smem_u32(smem);
    const uint32_t sbB = sbA + 3 * 16384;

    const int tid = threadIdx.x;
    const int wid = tid >> 5, lane = tid & 31;
    const int warp_m = wid >> 1, warp_n = wid & 1;
    const int r4 = lane >> 2, cc = lane & 3;
    const int m0 = blockIdx.y * 128, n0 = blockIdx.x * 128;
    const int Nvalid = (N - n0 < 128) ? (N - n0) : 128;

    const float* Arow = A + (size_t)m0 * lda;
    const float* Brow = B + (size_t)n0 * ldb;

    const int nc = (K + 31) / 32;

    float acc[2][8][4];
    #pragma unroll
    for (int i = 0; i < 2; i++)
        #pragma unroll
        for (int j = 0; j < 8; j++)
            #pragma unroll
            for (int v = 0; v < 4; v++) acc[i][j][v] = 0.f;

    // ---- cp.async per-thread assignment ----
    const int crow = tid >> 1;
    const int gb = (tid & 1) * 4;
    const bool bvalid = crow < Nvalid;
    const uint32_t swbase = (uint32_t)crow * 128;

    // ---- ldmatrix per-lane address offsets (within a 16KB stage) ----
    // tile layout per x4: lanes 0-7 rows+0..7 gran+gsel0, 8-15 rows+0..7 gran+1,
    //                     16-23 rows+8..15 gran, 24-31 rows+8..15 gran+1
    const int lrow8 = ((lane & 16) >> 1) + (lane & 7);  // 0..15
    const int gsel  = (lane >> 3) & 1;
    uint32_t aoff[2], boff[4];
    #pragma unroll
    for (int am = 0; am < 2; am++) {
        int row = warp_m * 32 + am * 16 + lrow8;
        aoff[am] = (uint32_t)row * 128 + ((uint32_t)((row & 7) ^ gsel) << 4);
    }
    #pragma unroll
    for (int nb = 0; nb < 4; nb++) {
        int row = warp_n * 64 + nb * 16 + lrow8;
        boff[nb] = (uint32_t)row * 128 + ((uint32_t)((row & 7) ^ gsel) << 4);
    }

    #define ISSUE_CHUNK(ch) do {                                            \
        int _st = (ch) % 3;                                                 \
        uint32_t _ab = sbA + _st * 16384;                                   \
        uint32_t _bb = sbB + _st * 16384;                                   \
        int _k0c = (ch) * 32;                                               \
        _Pragma("unroll")                                                   \
        for (int _j = 0; _j < 4; _j++) {                                    \
            int _g = gb + _j;                                               \
            int _k0 = _k0c + _g * 4;                                        \
            int _sz = (K - _k0) * 4;                                        \
            _sz = _sz < 0 ? 0 : (_sz > 16 ? 16 : _sz);                      \
            uint32_t _sw = swbase + ((uint32_t)(_g ^ (crow & 7)) << 4);     \
            const float* _sa = Arow + (size_t)crow * lda + (_sz ? _k0 : 0); \
            cp_async16(_ab + _sw, _sa, _sz);                                \
            int _szb = bvalid ? _sz : 0;                                    \
            const float* _sb = Brow + (_szb ? ((size_t)crow * ldb + _k0) : 0); \
            cp_async16(_bb + _sw, _sb, _szb);                               \
        }                                                                   \
    } while (0)

    ISSUE_CHUNK(0);
    CP_COMMIT();
    if (nc > 1) ISSUE_CHUNK(1);
    CP_COMMIT();

    for (int c = 0; c < nc; c++) {
        if (c + 2 < nc) ISSUE_CHUNK(c + 2);
        CP_COMMIT();
        CP_WAIT2();
        __syncthreads();

        const uint32_t pa = sbA + (c % 3) * 16384;
        const uint32_t pb = sbB + (c % 3) * 16384;
        const uint32_t Pa0 = pa + aoff[0], Pa1 = pa + aoff[1];
        const uint32_t Pb0 = pb + boff[0], Pb1 = pb + boff[1];
        const uint32_t Pb2 = pb + boff[2], Pb3 = pb + boff[3];

        #pragma unroll
        for (int ks = 0; ks < 4; ks++) {
            const uint32_t xm = (uint32_t)ks << 5;
            uint32_t a00, a01, a02, a03, a10, a11, a12, a13;
            ldsm_x4(a00, a01, a02, a03, Pa0 ^ xm);
            ldsm_x4(a10, a11, a12, a13, Pa1 ^ xm);
            uint32_t b0, b1, b2, b3;
            // note x4 reg order: r0=(rows,g), r1=(rows,g+1), r2=(rows+8,g), r3=(rows+8,g+1)
            // A fragment = {r0, r2, r1, r3}; B x4 covers two n-blocks.
            ldsm_x4(b0, b1, b2, b3, Pb0 ^ xm);
            mma_tf32(acc[0][0], a00, a02, a01, a03, b0, b1);
            mma_tf32(acc[0][1], a00, a02, a01, a03, b2, b3);
            mma_tf32(acc[1][0], a10, a12, a11, a13, b0, b1);
            mma_tf32(acc[1][1], a10, a12, a11, a13, b2, b3);
            ldsm_x4(b0, b1, b2, b3, Pb1 ^ xm);
            mma_tf32(acc[0][2], a00, a02, a01, a03, b0, b1);
            mma_tf32(acc[0][3], a00, a02, a01, a03, b2, b3);
            mma_tf32(acc[1][2], a10, a12, a11, a13, b0, b1);
            mma_tf32(acc[1][3], a10, a12, a11, a13, b2, b3);
            ldsm_x4(b0, b1, b2, b3, Pb2 ^ xm);
            mma_tf32(acc[0][4], a00, a02, a01, a03, b0, b1);
            mma_tf32(acc[0][5], a00, a02, a01, a03, b2, b3);
            mma_tf32(acc[1][4], a10, a12, a11, a13, b0, b1);
            mma_tf32(acc[1][5], a10, a12, a11, a13, b2, b3);
            ldsm_x4(b0, b1, b2, b3, Pb3 ^ xm);
            mma_tf32(acc[0][6], a00, a02, a01, a03, b0, b1);
            mma_tf32(acc[0][7], a00, a02, a01, a03, b2, b3);
            mma_tf32(acc[1][6], a10, a12, a11, a13, b0, b1);
            mma_tf32(acc[1][7], a10, a12, a11, a13, b2, b3);
        }
        __syncthreads();
    }

    #pragma unroll
    for (int am = 0; am < 2; am++) {
        #pragma unroll
        for (int p = 0; p < 2; p++) {
            int row = m0 + warp_m * 32 + am * 16 + p * 8 + r4;
            float* crowp = C + (size_t)row * ldc;
            #pragma unroll
            for (int an = 0; an < 8; an++) {
                int col = n0 + warp_n * 64 + an * 8 + cc * 2;
                if (col < N) {
                    float2 v = make_float2(acc[am][an][2 * p], acc[am][an][2 * p + 1]);
                    if (EPI == 1) {
                        float2 o = *(float2*)(crowp + col);
                        v.x += o.x; v.y += o.y;
                    } else if (EPI == 2) {
                        float2 bb2 = *(const float2*)(bias + col);
                        v.x = softplusf(v.x + bb2.x);
                        v.y = softplusf(v.y + bb2.y);
                    } else if (EPI == 3) {
                        v.x = tf32r(v.x); v.y = tf32r(v.y);
                    }
                    *(float2*)(crowp + col) = v;
                }
            }
        }
    }
    #undef ISSUE_CHUNK
}

// ---------------- Embedding gather ----------------
__global__ void gather_kernel(const int* __restrict__ ids,
                              const float* __restrict__ embed,
                              float* __restrict__ h) {
    int t = blockIdx.x;
    int c = threadIdx.x;
    int id = ids[t];
    const float4* src = (const float4*)(embed + (size_t)id * D_MODEL);
    float4* dst = (float4*)(h + (size_t)t * D_MODEL);
    dst[c] = src[c];
}

// ---------------- RMSNorm (per row of 768); optional tf32 rounding -------
__global__ void rmsnorm_kernel(const float* __restrict__ x, long in_stride,
                               const float* __restrict__ w,
                               float* __restrict__ y, long out_stride,
                               int do_round) {
    long r = blockIdx.x;
    const float* xr = x + r * in_stride;
    float* yr = y + r * out_stride;
    int tid = threadIdx.x; // 256
    float v0 = xr[tid], v1 = xr[tid + 256], v2 = xr[tid + 512];
    float s = v0 * v0 + v1 * v1 + v2 * v2;
    #pragma unroll
    for (int o = 16; o; o >>= 1) s += __shfl_xor_sync(0xffffffffu, s, o);
    __shared__ float ws[8];
    __shared__ float sc;
    if ((tid & 31) == 0) ws[tid >> 5] = s;
    __syncthreads();
    if (tid == 0) {
        float tsum = 0.f;
        #pragma unroll
        for (int k = 0; k < 8; k++) tsum += ws[k];
        sc = rsqrtf(tsum * (1.0f / D_MODEL) + EPS);
    }
    __syncthreads();
    float scale = sc;
    float o0 = v0 * scale * w[tid];
    float o1 = v1 * scale * w[tid + 256];
    float o2 = v2 * scale * w[tid + 512];
    if (do_round) { o0 = tf32r(o0); o1 = tf32r(o1); o2 = tf32r(o2); }
    yr[tid] = o0; yr[tid + 256] = o1; yr[tid + 512] = o2;
}

// ---------------- Depthwise causal conv (K=4) + bias + SiLU --------------
// 4 timesteps per thread: 7 loads -> 4 outputs.
__global__ void conv_silu_kernel(const float* __restrict__ proj,
                                 const float* __restrict__ cw,
                                 const float* __restrict__ cb,
                                 float* __restrict__ ut) {
    long idx = (long)blockIdx.x * 256 + threadIdx.x;
    if (idx >= (long)(T_TOT / 4) * I_INNER) return;
    int i = (int)(idx % I_INNER);
    long tq = idx / I_INNER;
    long t0 = tq * 4;
    int tl0 = (int)(t0 & (SEQ - 1));
    const long S = 2 * I_INNER;
    long base = t0 * S + i;
    float w0 = cw[i*4+0], w1 = cw[i*4+1], w2 = cw[i*4+2], w3 = cw[i*4+3];
    float bia = cb[i];

    float v[7];
    if (tl0 == 0) { v[0] = 0.f; v[1] = 0.f; v[2] = 0.f; }
    else {
        v[0] = proj[base - 3 * S];
        v[1] = proj[base - 2 * S];
        v[2] = proj[base - 1 * S];
    }
    v[3] = proj[base];
    v[4] = proj[base + 1 * S];
    v[5] = proj[base + 2 * S];
    v[6] = proj[base + 3 * S];

    float* up = ut + t0 * I_INNER + i;
    #pragma unroll
    for (int k = 0; k < 4; k++) {
        float s = bia;
        s = fmaf(w0, v[k], s);
        s = fmaf(w1, v[k + 1], s);
        s = fmaf(w2, v[k + 2], s);
        s = fmaf(w3, v[k + 3], s);
        float sig = 1.f / (1.f + __expf(-s));
        up[(size_t)k * I_INNER] = tf32r(s * sig);
    }
}

// ================= Chunked selective scan =================
__global__ __launch_bounds__(128)
void scan_phase1(const float* __restrict__ dt,
                 const float* __restrict__ ut,
                 const float* __restrict__ xdbl,
                 const float* __restrict__ A_log,
                 float* __restrict__ pA_out,
                 float* __restrict__ hf_out) {
    int i = blockIdx.x * 128 + threadIdx.x;
    int c = blockIdx.y;
    int b = blockIdx.z;
    float A[N_STATE], h[N_STATE], pA[N_STATE];
    #pragma unroll
    for (int n = 0; n < N_STATE; n++) {
        A[n] = -__expf(A_log[i * N_STATE + n]);
        h[n] = 0.f; pA[n] = 1.f;
    }
    int t0 = c * CH_LEN;
    const float* dtp = dt + (size_t)(b * SEQ + t0) * I_INNER + i;
    const float* up  = ut + (size_t)(b * SEQ + t0) * I_INNER + i;
    const float* xp  = xdbl + (size_t)(b * SEQ + t0) * 80;
    for (int t = 0; t < CH_LEN; t++) {
        float d = dtp[(size_t)t * I_INNER];
        float u = up[(size_t)t * I_INNER];
        float du = d * u;
        const float* xr = xp + (size_t)t * 80;
        #pragma unroll
        for (int n = 0; n < N_STATE; n++) {
            float Bn = xr[48 + n];
            float dA = __expf(d * A[n]);
            pA[n] *= dA;
            h[n] = fmaf(dA, h[n], du * Bn);
        }
    }
    size_t off = (size_t)((b * NCHUNK + c) * I_INNER + i) * N_STATE;
    #pragma unroll
    for (int n = 0; n < N_STATE; n++) {
        pA_out[off + n] = pA[n];
        hf_out[off + n] = h[n];
    }
}

__global__ void scan_phase2(const float* __restrict__ pA,
                            const float* __restrict__ hf,
                            float* __restrict__ hin) {
    int ch = blockIdx.x * 128 + threadIdx.x;
    if (ch >= BATCH * I_INNER) return;
    int b = ch / I_INNER, i = ch % I_INNER;
    float h[N_STATE];
    #pragma unroll
    for (int n = 0; n < N_STATE; n++) h[n] = 0.f;
    for (int c = 0; c < NCHUNK; c++) {
        size_t off = (size_t)((b * NCHUNK + c) * I_INNER + i) * N_STATE;
        #pragma unroll
        for (int n = 0; n < N_STATE; n++) {
            hin[off + n] = h[n];
            h[n] = fmaf(pA[off + n], h[n], hf[off + n]);
        }
    }
}

__global__ __launch_bounds__(128)
void scan_phase3(const float* __restrict__ dt,
                 const float* __restrict__ ut,
                 const float* __restrict__ xdbl,
                 const float* __restrict__ A_log,
                 const float* __restrict__ Dp,
                 const float* __restrict__ proj,
                 const float* __restrict__ hin,
                 float* __restrict__ y) {
    int i = blockIdx.x * 128 + threadIdx.x;
    int c = blockIdx.y;
    int b = blockIdx.z;
    float A[N_STATE], h[N_STATE];
    size_t soff = (size_t)((b * NCHUNK + c) * I_INNER + i) * N_STATE;
    #pragma unroll
    for (int n = 0; n < N_STATE; n++) {
        A[n] = -__expf(A_log[i * N_STATE + n]);
        h[n] = hin[soff + n];
    }
    float Di = Dp[i];
    int t0 = c * CH_LEN;
    const float* dtp = dt + (size_t)(b * SEQ + t0) * I_INNER + i;
    const float* up  = ut + (size_t)(b * SEQ + t0) * I_INNER + i;
    const float* gp  = proj + (size_t)(b * SEQ + t0) * 2 * I_INNER + I_INNER + i;
    const float* xp  = xdbl + (size_t)(b * SEQ + t0) * 80;
    float* yp        = y + (size_t)(b * SEQ + t0) * I_INNER + i;
    for (int t = 0; t < CH_LEN; t++) {
        float d = dtp[(size_t)t * I_INNER];
        float u = up[(size_t)t * I_INNER];
        float du = d * u;
        const float* xr = xp + (size_t)t * 80;
        float acc = 0.f;
        #pragma unroll
        for (int n = 0; n < N_STATE; n++) {
            float Bn = xr[48 + n];
            float Cn = xr[64 + n];
            float dA = __expf(d * A[n]);
            h[n] = fmaf(dA, h[n], du * Bn);
            acc = fmaf(h[n], Cn, acc);
        }
        float g = gp[(size_t)t * 2 * I_INNER];
        float sig = 1.f / (1.f + __expf(-g));
        yp[(size_t)t * I_INNER] = tf32r((acc + u * Di) * (g * sig));
    }
}

// ---------------- Logits: out[b,v] = dot(hn[b], embed[v]) ----------------
__global__ void logits_kernel(const float* __restrict__ hn,
                              const float* __restrict__ embed,
                              float* __restrict__ out) {
    __shared__ float sh[BATCH * D_MODEL];
    int tid = threadIdx.x; // 256
    for (int j = tid; j < BATCH * D_MODEL; j += 256) sh[j] = hn[j];
    __syncthreads();
    int warp = tid >> 5, lane = tid & 31;
    int v = blockIdx.x * 8 + warp;
    if (v >= VOCAB) return;
    const float* e = embed + (size_t)v * D_MODEL;
    float a0 = 0.f, a1 = 0.f, a2 = 0.f, a3 = 0.f;
    for (int j = lane; j < D_MODEL; j += 32) {
        float ev = e[j];
        a0 = fmaf(ev, sh[j], a0);
        a1 = fmaf(ev, sh[D_MODEL + j], a1);
        a2 = fmaf(ev, sh[2 * D_MODEL + j], a2);
        a3 = fmaf(ev, sh[3 * D_MODEL + j], a3);
    }
    #pragma unroll
    for (int o = 16; o; o >>= 1) {
        a0 += __shfl_down_sync(0xffffffffu, a0, o);
        a1 += __shfl_down_sync(0xffffffffu, a1, o);
        a2 += __shfl_down_sync(0xffffffffu, a2, o);
        a3 += __shfl_down_sync(0xffffffffu, a3, o);
    }
    if (lane == 0) {
        out[(size_t)0 * VOCAB + v] = a0;
        out[(size_t)1 * VOCAB + v] = a1;
        out[(size_t)2 * VOCAB + v] = a2;
        out[(size_t)3 * VOCAB + v] = a3;
    }
}

// ---------------- Launch ----------------
extern "C" void kernel_launch(void* const* d_in, const int* in_sizes, int n_in,
                              void* d_out, int out_size) {
    const int*   ids       = (const int*)  d_in[0];
    const float* embed     = (const float*)d_in[1];
    const float* norm_w    = (const float*)d_in[2];
    const float* in_proj_w = (const float*)d_in[3];
    const float* conv_w    = (const float*)d_in[4];
    const float* conv_b    = (const float*)d_in[5];
    const float* x_proj_w  = (const float*)d_in[6];
    const float* dt_proj_w = (const float*)d_in[7];
    const float* dt_proj_b = (const float*)d_in[8];
    const float* A_log     = (const float*)d_in[9];
    const float* D_param   = (const float*)d_in[10];
    const float* out_proj_w= (const float*)d_in[11];
    const float* norm_f_w  = (const float*)d_in[12];
    float* out = (float*)d_out;

    float *h, *x, *proj, *ut, *xdbl, *dt, *y, *hn, *pA, *hf, *hin;
    cudaGetSymbolAddress((void**)&h,    g_h);
    cudaGetSymbolAddress((void**)&x,    g_x);
    cudaGetSymbolAddress((void**)&proj, g_proj);
    cudaGetSymbolAddress((void**)&ut,   g_ut);
    cudaGetSymbolAddress((void**)&xdbl, g_xdbl);
    cudaGetSymbolAddress((void**)&dt,   g_dt);
    cudaGetSymbolAddress((void**)&y,    g_y);
    cudaGetSymbolAddress((void**)&hn,   g_hn);
    cudaGetSymbolAddress((void**)&pA,   g_pA);
    cudaGetSymbolAddress((void**)&hf,   g_hf);
    cudaGetSymbolAddress((void**)&hin,  g_hin);

    cudaFuncSetAttribute(tgemm<0>, cudaFuncAttributeMaxDynamicSharedMemorySize, TG_SMEM);
    cudaFuncSetAttribute(tgemm<1>, cudaFuncAttributeMaxDynamicSharedMemorySize, TG_SMEM);
    cudaFuncSetAttribute(tgemm<2>, cudaFuncAttributeMaxDynamicSharedMemorySize, TG_SMEM);
    cudaFuncSetAttribute(tgemm<3>, cudaFuncAttributeMaxDynamicSharedMemorySize, TG_SMEM);

    gather_kernel<<<T_TOT, 192>>>(ids, embed, h);

    for (int l = 0; l < L_LAYERS; l++) {
        rmsnorm_kernel<<<T_TOT, 256>>>(h, D_MODEL, norm_w + l * D_MODEL, x, D_MODEL, 1);

        // proj = x @ in_proj_w^T   (8192 x 3072 x 768); weights truncated by HMMA
        tgemm<0><<<dim3(24, 64), 256, TG_SMEM>>>(
            x, D_MODEL, in_proj_w + (size_t)l * 2 * I_INNER * D_MODEL, D_MODEL,
            proj, 2 * I_INNER, 2 * I_INNER, D_MODEL, nullptr);

        conv_silu_kernel<<<((T_TOT / 4) * I_INNER + 255) / 256, 256>>>(
            proj, conv_w + (size_t)l * I_INNER * K_CONV, conv_b + (size_t)l * I_INNER, ut);

        // xdbl = ut @ x_proj_w^T   (8192 x 80 x 1536), tf32-rounded output
        tgemm<3><<<dim3(1, 64), 256, TG_SMEM>>>(
            ut, I_INNER, x_proj_w + (size_t)l * 80 * I_INNER, I_INNER,
            xdbl, 80, 80, I_INNER, nullptr);

        // dt = softplus(dt_r @ dt_proj_w^T + b)   (8192 x 1536 x 48)
        tgemm<2><<<dim3(12, 64), 256, TG_SMEM>>>(
            xdbl, 80, dt_proj_w + (size_t)l * I_INNER * DT_RANK, DT_RANK,
            dt, I_INNER, I_INNER, DT_RANK, dt_proj_b + (size_t)l * I_INNER);

        // chunked parallel scan
        const float* Al = A_log + (size_t)l * I_INNER * N_STATE;
        scan_phase1<<<dim3(I_INNER / 128, NCHUNK, BATCH), 128>>>(
            dt, ut, xdbl, Al, pA, hf);
        scan_phase2<<<(BATCH * I_INNER + 127) / 128, 128>>>(pA, hf, hin);
        scan_phase3<<<dim3(I_INNER / 128, NCHUNK, BATCH), 128>>>(
            dt, ut, xdbl, Al, D_param + (size_t)l * I_INNER, proj, hin, y);

        // h += y @ out_proj_w^T    (8192 x 768 x 1536)
        tgemm<1><<<dim3(6, 64), 256, TG_SMEM>>>(
            y, I_INNER, out_proj_w + (size_t)l * D_MODEL * I_INNER, I_INNER,
            h, D_MODEL, D_MODEL, I_INNER, nullptr);
    }

    rmsnorm_kernel<<<BATCH, 256>>>(h + (size_t)(SEQ - 1) * D_MODEL,
                                   (long)SEQ * D_MODEL, norm_f_w, hn, D_MODEL, 0);
    logits_kernel<<<(VOCAB + 7) / 8, 256>>>(hn, embed, out);
}

// round 6
// speedup vs baseline: 1.1004x; 1.1004x over previous
#include <cuda_runtime.h>
#include <cuda_bf16.h>
#include <math.h>
#include <stdint.h>

// ---------------- Problem constants ----------------
#define BATCH 4
#define SEQ   2048
#define T_TOT (BATCH*SEQ)      // 8192
#define D_MODEL 768
#define L_LAYERS 4
#define N_STATE 16
#define K_CONV  4
#define I_INNER 1536           // 2*D_MODEL
#define DT_RANK 48
#define VOCAB 32000
#define EPS 1e-5f

// chunked scan config
#define CH_LEN 128
#define NCHUNK (SEQ / CH_LEN)   // 16

// ---------------- Scratch (static device globals; no allocs) ----------------
__device__ float g_h   [(size_t)T_TOT * D_MODEL];
__device__ float g_x   [(size_t)T_TOT * D_MODEL];
__device__ float g_proj[(size_t)T_TOT * 2 * I_INNER];
__device__ float g_ut  [(size_t)T_TOT * I_INNER];
__device__ float g_xdbl[(size_t)T_TOT * 80];
__device__ float g_dt  [(size_t)T_TOT * I_INNER];
__device__ float g_y   [(size_t)T_TOT * I_INNER];
__device__ float g_hn  [BATCH * D_MODEL];
// chunked-scan state: layout [b][c][i][n]
__device__ float g_pA  [(size_t)BATCH * NCHUNK * I_INNER * N_STATE];
__device__ float g_hf  [(size_t)BATCH * NCHUNK * I_INNER * N_STATE];
__device__ float g_hin [(size_t)BATCH * NCHUNK * I_INNER * N_STATE];

// ---------------- small helpers ----------------
__device__ __forceinline__ uint32_t smem_u32(const void* p) {
    uint32_t a;
    asm("{ .reg .u64 t; cvta.to.shared.u64 t, %1; cvt.u32.u64 %0, t; }"
        : "=r"(a) : "l"(p));
    return a;
}
__device__ __forceinline__ float tf32r(float x) {
    uint32_t r;
    asm("cvt.rna.tf32.f32 %0, %1;" : "=r"(r) : "f"(x));
    return __uint_as_float(r);
}
__device__ __forceinline__ void cp_async16(uint32_t dst, const void* src, int sz) {
    asm volatile("cp.async.cg.shared.global [%0], [%1], 16, %2;"
                 :: "r"(dst), "l"(src), "r"(sz) : "memory");
}
#define CP_COMMIT() asm volatile("cp.async.commit_group;" ::: "memory")
#define CP_WAIT1()  asm volatile("cp.async.wait_group 1;" ::: "memory")

__device__ __forceinline__ void mma_tf32(float* d, uint32_t a0, uint32_t a1,
                                         uint32_t a2, uint32_t a3,
                                         uint32_t b0, uint32_t b1) {
    asm volatile(
        "mma.sync.aligned.m16n8k8.row.col.f32.tf32.tf32.f32 "
        "{%0,%1,%2,%3}, {%4,%5,%6,%7}, {%8,%9}, {%0,%1,%2,%3};"
        : "+f"(d[0]), "+f"(d[1]), "+f"(d[2]), "+f"(d[3])
        : "r"(a0), "r"(a1), "r"(a2), "r"(a3), "r"(b0), "r"(b1));
}

__device__ __forceinline__ void ldsm_x4(uint32_t& r0, uint32_t& r1,
                                        uint32_t& r2, uint32_t& r3, uint32_t addr) {
    asm volatile("ldmatrix.sync.aligned.m8n8.x4.shared.b16 {%0,%1,%2,%3}, [%4];"
                 : "=r"(r0), "=r"(r1), "=r"(r2), "=r"(r3) : "r"(addr));
}

__device__ __forceinline__ float softplusf(float v) {
    return (v > 20.f) ? v : log1pf(__expf(v));
}

// ================= tensor-core tf32 GEMM (mma.sync m16n8k8 + ldmatrix) ======
// C[m,n] = sum_k A[m,k]*B[n,k].  A: 8192 x K rm, B: N x K rm.
// CTA tile 128x128, 8 warps (4m x 2n), warp tile 32x64, K chunks of 32,
// 3-stage cp.async pipeline (single __syncthreads per chunk), XOR-swizzled
// smem, batched ldmatrix fragment loads.
// EPI: 0 = store, 1 = C += acc, 2 = softplus(acc+bias), 3 = store tf32-rounded.
#define TG_SMEM (6 * 16384)

template<int EPI>
__global__ __launch_bounds__(256, 2)
void tgemm(const float* __restrict__ A, int lda,
           const float* __restrict__ B, int ldb,
           float* __restrict__ C, int ldc,
           int N, int K, const float* __restrict__ bias) {
    extern __shared__ char smem[];
    const uint32_t sbA = smem_u32(smem);
    const uint32_t sbB = sbA + 3 * 16384;

    const int tid = threadIdx.x;
    const int wid = tid >> 5, lane = tid & 31;
    const int warp_m = wid >> 1, warp_n = wid & 1;
    const int r4 = lane >> 2, cc = lane & 3;
    const int m0 = blockIdx.y * 128, n0 = blockIdx.x * 128;
    const int Nvalid = (N - n0 < 128) ? (N - n0) : 128;

    const float* Arow = A + (size_t)m0 * lda;
    const float* Brow = B + (size_t)n0 * ldb;

    const int nc = (K + 31) / 32;

    float acc[2][8][4];
    #pragma unroll
    for (int i = 0; i < 2; i++)
        #pragma unroll
        for (int j = 0; j < 8; j++)
            #pragma unroll
            for (int v = 0; v < 4; v++) acc[i][j][v] = 0.f;

    // ---- cp.async per-thread assignment ----
    const int crow = tid >> 1;
    const int gb = (tid & 1) * 4;
    const bool bvalid = crow < Nvalid;
    const uint32_t swbase = (uint32_t)crow * 128;

    // ---- ldmatrix per-lane address offsets (within a 16KB stage) ----
    const int lrow8 = ((lane & 16) >> 1) + (lane & 7);  // 0..15
    const int gsel  = (lane >> 3) & 1;
    uint32_t aoff[2], boff[4];
    #pragma unroll
    for (int am = 0; am < 2; am++) {
        int row = warp_m * 32 + am * 16 + lrow8;
        aoff[am] = (uint32_t)row * 128 + ((uint32_t)((row & 7) ^ gsel) << 4);
    }
    #pragma unroll
    for (int nb = 0; nb < 4; nb++) {
        int row = warp_n * 64 + nb * 16 + lrow8;
        boff[nb] = (uint32_t)row * 128 + ((uint32_t)((row & 7) ^ gsel) << 4);
    }

    #define ISSUE_CHUNK(ch) do {                                            \
        int _st = (ch) % 3;                                                 \
        uint32_t _ab = sbA + _st * 16384;                                   \
        uint32_t _bb = sbB + _st * 16384;                                   \
        int _k0c = (ch) * 32;                                               \
        _Pragma("unroll")                                                   \
        for (int _j = 0; _j < 4; _j++) {                                    \
            int _g = gb + _j;                                               \
            int _k0 = _k0c + _g * 4;                                        \
            int _sz = (K - _k0) * 4;                                        \
            _sz = _sz < 0 ? 0 : (_sz > 16 ? 16 : _sz);                      \
            uint32_t _sw = swbase + ((uint32_t)(_g ^ (crow & 7)) << 4);     \
            const float* _sa = Arow + (size_t)crow * lda + (_sz ? _k0 : 0); \
            cp_async16(_ab + _sw, _sa, _sz);                                \
            int _szb = bvalid ? _sz : 0;                                    \
            const float* _sb = Brow + (_szb ? ((size_t)crow * ldb + _k0) : 0); \
            cp_async16(_bb + _sw, _sb, _szb);                               \
        }                                                                   \
    } while (0)

    ISSUE_CHUNK(0);
    CP_COMMIT();
    if (nc > 1) ISSUE_CHUNK(1);
    CP_COMMIT();

    for (int c = 0; c < nc; c++) {
        CP_WAIT1();
        __syncthreads();
        if (c + 2 < nc) ISSUE_CHUNK(c + 2);
        CP_COMMIT();

        const uint32_t pa = sbA + (c % 3) * 16384;
        const uint32_t pb = sbB + (c % 3) * 16384;
        const uint32_t Pa0 = pa + aoff[0], Pa1 = pa + aoff[1];
        const uint32_t Pb0 = pb + boff[0], Pb1 = pb + boff[1];
        const uint32_t Pb2 = pb + boff[2], Pb3 = pb + boff[3];

        #pragma unroll
        for (int ks = 0; ks < 4; ks++) {
            const uint32_t xm = (uint32_t)ks << 5;
            uint32_t a00, a01, a02, a03, a10, a11, a12, a13;
            uint32_t b[16];
            // batch ALL fragment loads up front (ILP: 6 LDSM issue back-to-back)
            ldsm_x4(a00, a01, a02, a03, Pa0 ^ xm);
            ldsm_x4(a10, a11, a12, a13, Pa1 ^ xm);
            ldsm_x4(b[0],  b[1],  b[2],  b[3],  Pb0 ^ xm);
            ldsm_x4(b[4],  b[5],  b[6],  b[7],  Pb1 ^ xm);
            ldsm_x4(b[8],  b[9],  b[10], b[11], Pb2 ^ xm);
            ldsm_x4(b[12], b[13], b[14], b[15], Pb3 ^ xm);
            // x4 reg order: r0=(rows,g), r1=(rows,g+1), r2=(rows+8,g), r3=(rows+8,g+1)
            // A fragment = {r0, r2, r1, r3}; each B x4 covers two n-blocks.
            #pragma unroll
            for (int q = 0; q < 4; q++) {
                mma_tf32(acc[0][2*q+0], a00, a02, a01, a03, b[4*q+0], b[4*q+1]);
                mma_tf32(acc[0][2*q+1], a00, a02, a01, a03, b[4*q+2], b[4*q+3]);
                mma_tf32(acc[1][2*q+0], a10, a12, a11, a13, b[4*q+0], b[4*q+1]);
                mma_tf32(acc[1][2*q+1], a10, a12, a11, a13, b[4*q+2], b[4*q+3]);
            }
        }
    }

    #pragma unroll
    for (int am = 0; am < 2; am++) {
        #pragma unroll
        for (int p = 0; p < 2; p++) {
            int row = m0 + warp_m * 32 + am * 16 + p * 8 + r4;
            float* crowp = C + (size_t)row * ldc;
            #pragma unroll
            for (int an = 0; an < 8; an++) {
                int col = n0 + warp_n * 64 + an * 8 + cc * 2;
                if (col < N) {
                    float2 v = make_float2(acc[am][an][2 * p], acc[am][an][2 * p + 1]);
                    if (EPI == 1) {
                        float2 o = *(float2*)(crowp + col);
                        v.x += o.x; v.y += o.y;
                    } else if (EPI == 2) {
                        float2 bb2 = *(const float2*)(bias + col);
                        v.x = softplusf(v.x + bb2.x);
                        v.y = softplusf(v.y + bb2.y);
                    } else if (EPI == 3) {
                        v.x = tf32r(v.x); v.y = tf32r(v.y);
                    }
                    *(float2*)(crowp + col) = v;
                }
            }
        }
    }
    #undef ISSUE_CHUNK
}

// ---------------- Embedding gather ----------------
__global__ void gather_kernel(const int* __restrict__ ids,
                              const float* __restrict__ embed,
                              float* __restrict__ h) {
    int t = blockIdx.x;
    int c = threadIdx.x;
    int id = ids[t];
    const float4* src = (const float4*)(embed + (size_t)id * D_MODEL);
    float4* dst = (float4*)(h + (size_t)t * D_MODEL);
    dst[c] = src[c];
}

// ---------------- RMSNorm (per row of 768); optional tf32 rounding -------
__global__ void rmsnorm_kernel(const float* __restrict__ x, long in_stride,
                               const float* __restrict__ w,
                               float* __restrict__ y, long out_stride,
                               int do_round) {
    long r = blockIdx.x;
    const float* xr = x + r * in_stride;
    float* yr = y + r * out_stride;
    int tid = threadIdx.x; // 256
    float v0 = xr[tid], v1 = xr[tid + 256], v2 = xr[tid + 512];
    float s = v0 * v0 + v1 * v1 + v2 * v2;
    #pragma unroll
    for (int o = 16; o; o >>= 1) s += __shfl_xor_sync(0xffffffffu, s, o);
    __shared__ float ws[8];
    __shared__ float sc;
    if ((tid & 31) == 0) ws[tid >> 5] = s;
    __syncthreads();
    if (tid == 0) {
        float tsum = 0.f;
        #pragma unroll
        for (int k = 0; k < 8; k++) tsum += ws[k];
        sc = rsqrtf(tsum * (1.0f / D_MODEL) + EPS);
    }
    __syncthreads();
    float scale = sc;
    float o0 = v0 * scale * w[tid];
    float o1 = v1 * scale * w[tid + 256];
    float o2 = v2 * scale * w[tid + 512];
    if (do_round) { o0 = tf32r(o0); o1 = tf32r(o1); o2 = tf32r(o2); }
    yr[tid] = o0; yr[tid + 256] = o1; yr[tid + 512] = o2;
}

// ---------------- Depthwise causal conv (K=4) + bias + SiLU --------------
// 4 timesteps per thread: 7 loads -> 4 outputs.
__global__ void conv_silu_kernel(const float* __restrict__ proj,
                                 const float* __restrict__ cw,
                                 const float* __restrict__ cb,
                                 float* __restrict__ ut) {
    long idx = (long)blockIdx.x * 256 + threadIdx.x;
    if (idx >= (long)(T_TOT / 4) * I_INNER) return;
    int i = (int)(idx % I_INNER);
    long tq = idx / I_INNER;
    long t0 = tq * 4;
    int tl0 = (int)(t0 & (SEQ - 1));
    const long S = 2 * I_INNER;
    long base = t0 * S + i;
    float w0 = cw[i*4+0], w1 = cw[i*4+1], w2 = cw[i*4+2], w3 = cw[i*4+3];
    float bia = cb[i];

    float v[7];
    if (tl0 == 0) { v[0] = 0.f; v[1] = 0.f; v[2] = 0.f; }
    else {
        v[0] = proj[base - 3 * S];
        v[1] = proj[base - 2 * S];
        v[2] = proj[base - 1 * S];
    }
    v[3] = proj[base];
    v[4] = proj[base + 1 * S];
    v[5] = proj[base + 2 * S];
    v[6] = proj[base + 3 * S];

    float* up = ut + t0 * I_INNER + i;
    #pragma unroll
    for (int k = 0; k < 4; k++) {
        float s = bia;
        s = fmaf(w0, v[k], s);
        s = fmaf(w1, v[k + 1], s);
        s = fmaf(w2, v[k + 2], s);
        s = fmaf(w3, v[k + 3], s);
        float sig = 1.f / (1.f + __expf(-s));
        up[(size_t)k * I_INNER] = tf32r(s * sig);
    }
}

// ================= Chunked selective scan =================
__global__ __launch_bounds__(128)
void scan_phase1(const float* __restrict__ dt,
                 const float* __restrict__ ut,
                 const float* __restrict__ xdbl,
                 const float* __restrict__ A_log,
                 float* __restrict__ pA_out,
                 float* __restrict__ hf_out) {
    int i = blockIdx.x * 128 + threadIdx.x;
    int c = blockIdx.y;
    int b = blockIdx.z;
    float A[N_STATE], h[N_STATE], pA[N_STATE];
    #pragma unroll
    for (int n = 0; n < N_STATE; n++) {
        A[n] = -__expf(A_log[i * N_STATE + n]);
        h[n] = 0.f; pA[n] = 1.f;
    }
    int t0 = c * CH_LEN;
    const float* dtp = dt + (size_t)(b * SEQ + t0) * I_INNER + i;
    const float* up  = ut + (size_t)(b * SEQ + t0) * I_INNER + i;
    const float* xp  = xdbl + (size_t)(b * SEQ + t0) * 80;
    for (int t = 0; t < CH_LEN; t++) {
        float d = dtp[(size_t)t * I_INNER];
        float u = up[(size_t)t * I_INNER];
        float du = d * u;
        const float* xr = xp + (size_t)t * 80;
        #pragma unroll
        for (int n = 0; n < N_STATE; n++) {
            float Bn = xr[48 + n];
            float dA = __expf(d * A[n]);
            pA[n] *= dA;
            h[n] = fmaf(dA, h[n], du * Bn);
        }
    }
    size_t off = (size_t)((b * NCHUNK + c) * I_INNER + i) * N_STATE;
    #pragma unroll
    for (int n = 0; n < N_STATE; n++) {
        pA_out[off + n] = pA[n];
        hf_out[off + n] = h[n];
    }
}

__global__ void scan_phase2(const float* __restrict__ pA,
                            const float* __restrict__ hf,
                            float* __restrict__ hin) {
    int ch = blockIdx.x * 128 + threadIdx.x;
    if (ch >= BATCH * I_INNER) return;
    int b = ch / I_INNER, i = ch % I_INNER;
    float h[N_STATE];
    #pragma unroll
    for (int n = 0; n < N_STATE; n++) h[n] = 0.f;
    for (int c = 0; c < NCHUNK; c++) {
        size_t off = (size_t)((b * NCHUNK + c) * I_INNER + i) * N_STATE;
        #pragma unroll
        for (int n = 0; n < N_STATE; n++) {
            hin[off + n] = h[n];
            h[n] = fmaf(pA[off + n], h[n], hf[off + n]);
        }
    }
}

__global__ __launch_bounds__(128)
void scan_phase3(const float* __restrict__ dt,
                 const float* __restrict__ ut,
                 const float* __restrict__ xdbl,
                 const float* __restrict__ A_log,
                 const float* __restrict__ Dp,
                 const float* __restrict__ proj,
                 const float* __restrict__ hin,
                 float* __restrict__ y) {
    int i = blockIdx.x * 128 + threadIdx.x;
    int c = blockIdx.y;
    int b = blockIdx.z;
    float A[N_STATE], h[N_STATE];
    size_t soff = (size_t)((b * NCHUNK + c) * I_INNER + i) * N_STATE;
    #pragma unroll
    for (int n = 0; n < N_STATE; n++) {
        A[n] = -__expf(A_log[i * N_STATE + n]);
        h[n] = hin[soff + n];
    }
    float Di = Dp[i];
    int t0 = c * CH_LEN;
    const float* dtp = dt + (size_t)(b * SEQ + t0) * I_INNER + i;
    const float* up  = ut + (size_t)(b * SEQ + t0) * I_INNER + i;
    const float* gp  = proj + (size_t)(b * SEQ + t0) * 2 * I_INNER + I_INNER + i;
    const float* xp  = xdbl + (size_t)(b * SEQ + t0) * 80;
    float* yp        = y + (size_t)(b * SEQ + t0) * I_INNER + i;
    for (int t = 0; t < CH_LEN; t++) {
        float d = dtp[(size_t)t * I_INNER];
        float u = up[(size_t)t * I_INNER];
        float du = d * u;
        const float* xr = xp + (size_t)t * 80;
        float acc = 0.f;
        #pragma unroll
        for (int n = 0; n < N_STATE; n++) {
            float Bn = xr[48 + n];
            float Cn = xr[64 + n];
            float dA = __expf(d * A[n]);
            h[n] = fmaf(dA, h[n], du * Bn);
            acc = fmaf(h[n], Cn, acc);
        }
        float g = gp[(size_t)t * 2 * I_INNER];
        float sig = 1.f / (1.f + __expf(-g));
        yp[(size_t)t * I_INNER] = tf32r((acc + u * Di) * (g * sig));
    }
}

// ---------------- Logits: out[b,v] = dot(hn[b], embed[v]) ----------------
__global__ void logits_kernel(const float* __restrict__ hn,
                              const float* __restrict__ embed,
                              float* __restrict__ out) {
    __shared__ float sh[BATCH * D_MODEL];
    int tid = threadIdx.x; // 256
    for (int j = tid; j < BATCH * D_MODEL; j += 256) sh[j] = hn[j];
    __syncthreads();
    int warp = tid >> 5, lane = tid & 31;
    int v = blockIdx.x * 8 + warp;
    if (v >= VOCAB) return;
    const float* e = embed + (size_t)v * D_MODEL;
    float a0 = 0.f, a1 = 0.f, a2 = 0.f, a3 = 0.f;
    for (int j = lane; j < D_MODEL; j += 32) {
        float ev = e[j];
        a0 = fmaf(ev, sh[j], a0);
        a1 = fmaf(ev, sh[D_MODEL + j], a1);
        a2 = fmaf(ev, sh[2 * D_MODEL + j], a2);
        a3 = fmaf(ev, sh[3 * D_MODEL + j], a3);
    }
    #pragma unroll
    for (int o = 16; o; o >>= 1) {
        a0 += __shfl_down_sync(0xffffffffu, a0, o);
        a1 += __shfl_down_sync(0xffffffffu, a1, o);
        a2 += __shfl_down_sync(0xffffffffu, a2, o);
        a3 += __shfl_down_sync(0xffffffffu, a3, o);
    }
    if (lane == 0) {
        out[(size_t)0 * VOCAB + v] = a0;
        out[(size_t)1 * VOCAB + v] = a1;
        out[(size_t)2 * VOCAB + v] = a2;
        out[(size_t)3 * VOCAB + v] = a3;
    }
}

// ---------------- Launch ----------------
extern "C" void kernel_launch(void* const* d_in, const int* in_sizes, int n_in,
                              void* d_out, int out_size) {
    const int*   ids       = (const int*)  d_in[0];
    const float* embed     = (const float*)d_in[1];
    const float* norm_w    = (const float*)d_in[2];
    const float* in_proj_w = (const float*)d_in[3];
    const float* conv_w    = (const float*)d_in[4];
    const float* conv_b    = (const float*)d_in[5];
    const float* x_proj_w  = (const float*)d_in[6];
    const float* dt_proj_w = (const float*)d_in[7];
    const float* dt_proj_b = (const float*)d_in[8];
    const float* A_log     = (const float*)d_in[9];
    const float* D_param   = (const float*)d_in[10];
    const float* out_proj_w= (const float*)d_in[11];
    const float* norm_f_w  = (const float*)d_in[12];
    float* out = (float*)d_out;

    float *h, *x, *proj, *ut, *xdbl, *dt, *y, *hn, *pA, *hf, *hin;
    cudaGetSymbolAddress((void**)&h,    g_h);
    cudaGetSymbolAddress((void**)&x,    g_x);
    cudaGetSymbolAddress((void**)&proj, g_proj);
    cudaGetSymbolAddress((void**)&ut,   g_ut);
    cudaGetSymbolAddress((void**)&xdbl, g_xdbl);
    cudaGetSymbolAddress((void**)&dt,   g_dt);
    cudaGetSymbolAddress((void**)&y,    g_y);
    cudaGetSymbolAddress((void**)&hn,   g_hn);
    cudaGetSymbolAddress((void**)&pA,   g_pA);
    cudaGetSymbolAddress((void**)&hf,   g_hf);
    cudaGetSymbolAddress((void**)&hin,  g_hin);

    cudaFuncSetAttribute(tgemm<0>, cudaFuncAttributeMaxDynamicSharedMemorySize, TG_SMEM);
    cudaFuncSetAttribute(tgemm<1>, cudaFuncAttributeMaxDynamicSharedMemorySize, TG_SMEM);
    cudaFuncSetAttribute(tgemm<2>, cudaFuncAttributeMaxDynamicSharedMemorySize, TG_SMEM);
    cudaFuncSetAttribute(tgemm<3>, cudaFuncAttributeMaxDynamicSharedMemorySize, TG_SMEM);

    gather_kernel<<<T_TOT, 192>>>(ids, embed, h);

    for (int l = 0; l < L_LAYERS; l++) {
        rmsnorm_kernel<<<T_TOT, 256>>>(h, D_MODEL, norm_w + l * D_MODEL, x, D_MODEL, 1);

        // proj = x @ in_proj_w^T   (8192 x 3072 x 768)
        tgemm<0><<<dim3(24, 64), 256, TG_SMEM>>>(
            x, D_MODEL, in_proj_w + (size_t)l * 2 * I_INNER * D_MODEL, D_MODEL,
            proj, 2 * I_INNER, 2 * I_INNER, D_MODEL, nullptr);

        conv_silu_kernel<<<((T_TOT / 4) * I_INNER + 255) / 256, 256>>>(
            proj, conv_w + (size_t)l * I_INNER * K_CONV, conv_b + (size_t)l * I_INNER, ut);

        // xdbl = ut @ x_proj_w^T   (8192 x 80 x 1536), tf32-rounded output
        tgemm<3><<<dim3(1, 64), 256, TG_SMEM>>>(
            ut, I_INNER, x_proj_w + (size_t)l * 80 * I_INNER, I_INNER,
            xdbl, 80, 80, I_INNER, nullptr);

        // dt = softplus(dt_r @ dt_proj_w^T + b)   (8192 x 1536 x 48)
        tgemm<2><<<dim3(12, 64), 256, TG_SMEM>>>(
            xdbl, 80, dt_proj_w + (size_t)l * I_INNER * DT_RANK, DT_RANK,
            dt, I_INNER, I_INNER, DT_RANK, dt_proj_b + (size_t)l * I_INNER);

        // chunked parallel scan
        const float* Al = A_log + (size_t)l * I_INNER * N_STATE;
        scan_phase1<<<dim3(I_INNER / 128, NCHUNK, BATCH), 128>>>(
            dt, ut, xdbl, Al, pA, hf);
        scan_phase2<<<(BATCH * I_INNER + 127) / 128, 128>>>(pA, hf, hin);
        scan_phase3<<<dim3(I_INNER / 128, NCHUNK, BATCH), 128>>>(
            dt, ut, xdbl, Al, D_param + (size_t)l * I_INNER, proj, hin, y);

        // h += y @ out_proj_w^T    (8192 x 768 x 1536)
        tgemm<1><<<dim3(6, 64), 256, TG_SMEM>>>(
            y, I_INNER, out_proj_w + (size_t)l * D_MODEL * I_INNER, I_INNER,
            h, D_MODEL, D_MODEL, I_INNER, nullptr);
    }

    rmsnorm_kernel<<<BATCH, 256>>>(h + (size_t)(SEQ - 1) * D_MODEL,
                                   (long)SEQ * D_MODEL, norm_f_w, hn, D_MODEL, 0);
    logits_kernel<<<(VOCAB + 7) / 8, 256>>>(hn, embed, out);
}